// round 9
// baseline (speedup 1.0000x reference)
#include <cuda_runtime.h>
#include <math_constants.h>
#include <cstdint>
#include <cstddef>

#define DEMB 768
#define KSEL 32
#define K2   128               // blockmin threshold rank
#define TILE_N 128
#define KC   32                // k elements per chunk
#define NCH  (DEMB / KC)       // 24
#define MAXB 256
#define MAXN 200000
#define MAXT ((MAXN + TILE_N - 1) / TILE_N)   // 1563
#define CCAP 1024
#define NL   7                 // blockmins cached per thread (7*256 >= MAXT)

// stage layout: A s8 256 rows x 48B pitch (32B data), B s8 128 rows x 48B pitch
#define A_PITCH 48
#define B_PITCH 48
#define A_BYTES (256 * A_PITCH)            // 12288
#define B_BYTES (128 * B_PITCH)            // 6144
#define STAGE_BYTES (A_BYTES + B_BYTES)    // 18432
#define STAGES 4

// ---- device scratch ----
__device__ __align__(16) uint8_t g_Q8[MAXB * DEMB];
__device__ __align__(16) uint8_t g_X8[(size_t)MAXN * DEMB];
__device__ __align__(16) float   g_x2g[MAXN];
__device__ __align__(16) float   g_S[(size_t)MAXB * (size_t)MAXN];
__device__ __align__(16) float   g_blkmin[MAXB * MAXT];

__device__ __forceinline__ uint32_t smem_u32(const void* p) {
    uint32_t a;
    asm("{ .reg .u64 t; cvta.to.shared.u64 t, %1; cvt.u32.u64 %0, t; }" : "=r"(a) : "l"(p));
    return a;
}
__device__ __forceinline__ void cp16(uint32_t dst, const void* src) {
    asm volatile("cp.async.ca.shared.global [%0], [%1], 16;" :: "r"(dst), "l"(src));
}
#define CP_COMMIT() asm volatile("cp.async.commit_group;" ::: "memory")
#define CP_WAIT2()  asm volatile("cp.async.wait_group 2;" ::: "memory")

__device__ __forceinline__ int q8(float f) {
    return __float2int_rn(fminf(fmaxf(f * 32.f, -127.f), 127.f));
}
__device__ __forceinline__ uint32_t pack_s8(float f0, float f1, float f2, float f3) {
    return (uint32_t)(q8(f0) & 255) | ((uint32_t)(q8(f1) & 255) << 8) |
           ((uint32_t)(q8(f2) & 255) << 16) | ((uint32_t)(q8(f3) & 255) << 24);
}
__device__ __forceinline__ void mma_s8(int* c, const uint32_t* a, const uint32_t* b) {
    asm volatile(
        "mma.sync.aligned.m16n8k32.row.col.s32.s8.s8.s32 "
        "{%0,%1,%2,%3}, {%4,%5,%6,%7}, {%8,%9}, {%0,%1,%2,%3};"
        : "+r"(c[0]), "+r"(c[1]), "+r"(c[2]), "+r"(c[3])
        : "r"(a[0]), "r"(a[1]), "r"(a[2]), "r"(a[3]), "r"(b[0]), "r"(b[1]));
}
__device__ __forceinline__ unsigned enc(float f) {
    unsigned u = __float_as_uint(f);
    return (u & 0x80000000u) ? ~u : (u | 0x80000000u);
}
__device__ __forceinline__ float dec(unsigned u) {
    u = (u & 0x80000000u) ? (u & 0x7fffffffu) : ~u;
    return __uint_as_float(u);
}
__device__ __forceinline__ unsigned long long mkkey(float v, int idx) {
    return ((unsigned long long)enc(v) << 32) | (unsigned)idx;
}

// ---------------- Q fp32 -> s8 (zero-pad to MAXB rows) ----------------
__global__ void convq_kernel(const float* __restrict__ Q, int total) {
    int i = blockIdx.x * blockDim.x + threadIdx.x;
    if (i < MAXB * DEMB / 4) {
        int e = i * 4;
        float4 v = make_float4(0.f, 0.f, 0.f, 0.f);
        if (e < total) v = *(const float4*)&Q[e];
        ((uint32_t*)g_Q8)[i] = pack_s8(v.x, v.y, v.z, v.w);
    }
}

// ---------------- X fp32 -> s8 + exact row norms (one read of X) ----------------
__global__ void convx_kernel(const float* __restrict__ X, int N) {
    int w = (int)((blockIdx.x * blockDim.x + threadIdx.x) >> 5);
    int lane = threadIdx.x & 31;
    if (w >= N) return;
    const float4* src = (const float4*)(X + (size_t)w * DEMB);
    uint32_t* dst = (uint32_t*)(g_X8 + (size_t)w * DEMB);
    float s = 0.f;
    #pragma unroll
    for (int i = lane; i < DEMB / 4; i += 32) {
        float4 v = src[i];
        dst[i] = pack_s8(v.x, v.y, v.z, v.w);
        s = fmaf(v.x, v.x, fmaf(v.y, v.y, fmaf(v.z, v.z, fmaf(v.w, v.w, s))));
    }
    #pragma unroll
    for (int off = 16; off > 0; off >>= 1) s += __shfl_xor_sync(0xffffffffu, s, off);
    if (lane == 0) g_x2g[w] = s;
}

// ---------------- INT8 MMA GEMM, M=256 x N-tile=128 ----------------
__global__ __launch_bounds__(512, 1)
void gemm_s8_kernel(int B, int N, int ntiles)
{
    extern __shared__ __align__(16) char dsm[];
    __shared__ float    x2p[TILE_N];
    __shared__ unsigned bmu[256];

    const int tid  = threadIdx.x;
    const int lane = tid & 31;
    const int warp = tid >> 5;
    const int wm = warp >> 2, wn = warp & 3;
    const int fr = lane >> 2, fc = lane & 3;
    const int n0 = blockIdx.x * TILE_N;

    const uint32_t sb = smem_u32(dsm);

    // A cp.async: 256 rows x 2 x 16B chunks, one per thread
    const int rA = tid >> 1, hA = tid & 1;
    const char* asrc = (const char*)g_Q8 + (size_t)rA * DEMB + hA * 16;
    const uint32_t adst = sb + rA * A_PITCH + hA * 16;

    // B cp.async: 128 rows x 2 x 16B chunks, threads 0..255
    const int rB = (tid & 255) >> 1, hB = tid & 1;
    const char* bsrc = (const char*)g_X8 + (size_t)min(n0 + rB, N - 1) * DEMB + hB * 16;
    const uint32_t bdst = sb + A_BYTES + rB * B_PITCH + hB * 16;
    const bool doB = tid < 256;

    if (tid < 256) bmu[tid] = 0xFFFFFFFFu;
    if (tid < TILE_N) x2p[tid] = g_x2g[min(n0 + tid, N - 1)];

    // prologue: stages 0..2
    #pragma unroll
    for (int s = 0; s < 3; s++) {
        cp16(adst + s * STAGE_BYTES, asrc + s * KC);
        if (doB) cp16(bdst + s * STAGE_BYTES, bsrc + s * KC);
        CP_COMMIT();
    }

    int acc[4][4][4];
    #pragma unroll
    for (int mi = 0; mi < 4; mi++)
        #pragma unroll
        for (int ni = 0; ni < 4; ni++)
            #pragma unroll
            for (int r = 0; r < 4; r++) acc[mi][ni][r] = 0;

    for (int ch = 0; ch < NCH; ch++) {
        const int st = ch & 3;
        CP_WAIT2();
        __syncthreads();   // completion visibility AND compute-done-before-overwrite

        if (ch + 3 < NCH) {
            const int so = ((ch + 3) & 3) * STAGE_BYTES;
            const int ko = (ch + 3) * KC;
            cp16(adst + so, asrc + ko);
            if (doB) cp16(bdst + so, bsrc + ko);
        }
        CP_COMMIT();

        const char* Ab = dsm + st * STAGE_BYTES;
        const char* Bb = Ab + A_BYTES;

        // B fragments (conflict-free, pitch 48)
        uint32_t bf[4][2];
        #pragma unroll
        for (int ni = 0; ni < 4; ni++) {
            const int n = wn * 32 + ni * 8 + fr;
            bf[ni][0] = *(const uint32_t*)(Bb + n * B_PITCH + fc * 4);
            bf[ni][1] = *(const uint32_t*)(Bb + n * B_PITCH + 16 + fc * 4);
        }

        // A fragments + MMAs
        #pragma unroll
        for (int mi = 0; mi < 4; mi++) {
            const int row = wm * 64 + mi * 16 + fr;
            uint32_t a[4];
            a[0] = *(const uint32_t*)(Ab + row * A_PITCH + fc * 4);
            a[1] = *(const uint32_t*)(Ab + (row + 8) * A_PITCH + fc * 4);
            a[2] = *(const uint32_t*)(Ab + row * A_PITCH + 16 + fc * 4);
            a[3] = *(const uint32_t*)(Ab + (row + 8) * A_PITCH + 16 + fc * 4);
            #pragma unroll
            for (int ni = 0; ni < 4; ni++)
                mma_s8(acc[mi][ni], a, bf[ni]);
        }
        // no trailing sync: next iteration's leading __syncthreads orders the overwrite
    }
    __syncthreads();

    // ---- epilogue: d2 = x2 - 2*dot/1024, float2 stores + blockmin ----
    const float SC = -2.0f / 1024.0f;
    #pragma unroll
    for (int mi = 0; mi < 4; mi++) {
        const int R = wm * 64 + mi * 16 + fr;
        float mn0 = CUDART_INF_F, mn1 = CUDART_INF_F;
        #pragma unroll
        for (int ni = 0; ni < 4; ni++) {
            const int c = wn * 32 + ni * 8 + 2 * fc;
            const int n = n0 + c;
            const bool ok0 = n < N, ok1 = (n + 1) < N;
            float x2c = x2p[c], x2d = x2p[c + 1];
            float v0 = fmaf(SC, (float)acc[mi][ni][0], x2c);
            float v1 = fmaf(SC, (float)acc[mi][ni][1], x2d);
            float v2 = fmaf(SC, (float)acc[mi][ni][2], x2c);
            float v3 = fmaf(SC, (float)acc[mi][ni][3], x2d);
            if (R < B) {
                if (ok0 && ok1) *(float2*)&g_S[(size_t)R * N + n] = make_float2(v0, v1);
                else if (ok0) g_S[(size_t)R * N + n] = v0;
            }
            if (R + 8 < B) {
                if (ok0 && ok1) *(float2*)&g_S[(size_t)(R + 8) * N + n] = make_float2(v2, v3);
                else if (ok0) g_S[(size_t)(R + 8) * N + n] = v2;
            }
            if (ok0) { mn0 = fminf(mn0, v0); mn1 = fminf(mn1, v2); }
            if (ok1) { mn0 = fminf(mn0, v1); mn1 = fminf(mn1, v3); }
        }
        #pragma unroll
        for (int off = 1; off < 4; off <<= 1) {
            mn0 = fminf(mn0, __shfl_xor_sync(0xffffffffu, mn0, off));
            mn1 = fminf(mn1, __shfl_xor_sync(0xffffffffu, mn1, off));
        }
        if (fc == 0) {
            atomicMin(&bmu[R], enc(mn0));
            atomicMin(&bmu[R + 8], enc(mn1));
        }
    }
    __syncthreads();
    if (tid < 256)
        g_blkmin[tid * ntiles + blockIdx.x] = dec(bmu[tid]);
}

// ---------------- select v3: 2 queries/CTA, named barriers, binary-search t0 ----------------
__global__ __launch_bounds__(512)
void select_kernel(const float* __restrict__ Q, const int* __restrict__ qsys,
                   const float* __restrict__ X, const float* __restrict__ Y,
                   const int* __restrict__ sys, const float* __restrict__ W,
                   const float* __restrict__ bias, float* __restrict__ out,
                   int B, int N, int ntiles)
{
    __shared__ float qs[2][DEMB];
    __shared__ unsigned long long buf[2][CCAP];
    __shared__ int   cand[2][CCAP];
    __shared__ int   blist[2][CCAP];
    __shared__ float red[2][8];
    __shared__ int   wcnt[2][8];
    __shared__ int   sh_cnt[2], sh_nblk[2];

    const int tid  = threadIdx.x;
    const int half = tid >> 8;
    const int htid = tid & 255;
    const int hw   = htid >> 5;        // warp within half (0..7)
    const int lane = tid & 31;
    const int hbar = half + 1;
    const int b    = blockIdx.x * 2 + half;

    #define HBAR() asm volatile("bar.sync %0, 256;" :: "r"(hbar) : "memory")

    // ---- query row + q2 ----
    float q2p = 0.f;
    for (int k = htid; k < DEMB; k += 256) {
        float v = Q[(size_t)b * DEMB + k];
        qs[half][k] = v; q2p = fmaf(v, v, q2p);
    }
    #pragma unroll
    for (int off = 16; off > 0; off >>= 1) q2p += __shfl_xor_sync(0xffffffffu, q2p, off);
    if (lane == 0) red[half][hw] = q2p;
    if (htid == 0) { sh_cnt[half] = 0; sh_nblk[half] = 0; }
    HBAR();
    float q2 = 0.f;
    #pragma unroll
    for (int w = 0; w < 8; w++) q2 += red[half][w];

    // ---- cache blockmins (encoded) in registers ----
    const float* bmrow = &g_blkmin[b * ntiles];
    uint32_t loc[NL];
    #pragma unroll
    for (int i = 0; i < NL; i++) {
        int idx = i * 256 + htid;
        loc[i] = (idx < ntiles) ? enc(bmrow[idx]) : 0xFFFFFFFFu;
    }

    // ---- bitwise binary search: t0enc = K2-th smallest encoded blockmin ----
    uint32_t r = 0;
    for (int bitp = 31; bitp >= 0; bitp--) {
        uint32_t trial = r | (1u << bitp);
        int c = 0;
        #pragma unroll
        for (int i = 0; i < NL; i++) c += (loc[i] < trial);
        #pragma unroll
        for (int off = 16; off > 0; off >>= 1) c += __shfl_xor_sync(0xffffffffu, c, off);
        if (lane == 0) wcnt[half][hw] = c;
        HBAR();
        int tot = 0;
        #pragma unroll
        for (int w = 0; w < 8; w++) tot += wcnt[half][w];
        if (tot < K2) r = trial;
        HBAR();   // wcnt reuse next iteration
    }
    const uint32_t t0enc = r;
    const float t0 = dec(t0enc);

    // ---- qualifying blocks ----
    #pragma unroll
    for (int i = 0; i < NL; i++) {
        int idx = i * 256 + htid;
        if (idx < ntiles && loc[i] <= t0enc) {
            int p = atomicAdd(&sh_nblk[half], 1);
            if (p < CCAP) blist[half][p] = idx;
        }
    }
    HBAR();
    int nblk = sh_nblk[half]; if (nblk > CCAP) nblk = CCAP;

    // ---- gather candidate indices (values <= t0) ----
    const float* srow = &g_S[(size_t)b * N];
    for (int e = htid; e < nblk * TILE_N; e += 256) {
        int blk = blist[half][e >> 7];
        int n = blk * TILE_N + (e & (TILE_N - 1));
        if (n < N) {
            float v = srow[n];
            if (v <= t0) {
                int p = atomicAdd(&sh_cnt[half], 1);
                if (p < CCAP) cand[half][p] = n;
            }
        }
    }
    HBAR();
    int cnt = sh_cnt[half]; if (cnt > CCAP) cnt = CCAP;

    int P = 64; while (P < cnt) P <<= 1;
    for (int i = htid; i < P; i += 256) buf[half][i] = ~0ULL;
    HBAR();

    // ---- exact fp32 refine of ALL candidates ----
    for (int c = hw; c < cnt; c += 8) {
        const int idx = cand[half][c];
        const float* xr = &X[(size_t)idx * DEMB];
        float dot = 0.f, xx = 0.f;
        for (int k = lane; k < DEMB; k += 32) {
            float xv = xr[k];
            dot = fmaf(qs[half][k], xv, dot);
            xx  = fmaf(xv, xv, xx);
        }
        #pragma unroll
        for (int off = 16; off > 0; off >>= 1) {
            dot += __shfl_xor_sync(0xffffffffu, dot, off);
            xx  += __shfl_xor_sync(0xffffffffu, xx,  off);
        }
        if (lane == 0) buf[half][c] = mkkey(fmaf(-2.f, dot, q2 + xx), idx);
    }
    HBAR();

    // ---- bitonic sort exact keys ascending ----
    for (int k = 2; k <= P; k <<= 1)
        for (int j = k >> 1; j > 0; j >>= 1) {
            for (int i = htid; i < P; i += 256) {
                int ixj = i ^ j;
                if (ixj > i) {
                    unsigned long long a = buf[half][i], c = buf[half][ixj];
                    if ((a > c) == ((i & k) == 0)) { buf[half][i] = c; buf[half][ixj] = a; }
                }
            }
            HBAR();
        }

    // ---- local layer + prefix softmax on ranks 0..31 ----
    if (htid < KSEL) {
        unsigned long long key = buf[half][htid];
        float d2v = dec((unsigned)(key >> 32));
        int   idx = (int)(key & 0xffffffffu);
        float sc  = Y[idx];
        float nd  = (sys[idx] == qsys[b]) ? fmaf(d2v, W[1], bias[1]) : fmaf(d2v, W[0], bias[0]);
        float neg = -nd;
        float mmax = neg;
        #pragma unroll
        for (int off = 16; off > 0; off >>= 1)
            mmax = fmaxf(mmax, __shfl_xor_sync(0xffffffffu, mmax, off));
        float w  = expf(neg - mmax);
        float ws = w * sc;
        float cw = w, cws = ws;
        #pragma unroll
        for (int off = 1; off < KSEL; off <<= 1) {
            float tw  = __shfl_up_sync(0xffffffffu, cw,  off);
            float tws = __shfl_up_sync(0xffffffffu, cws, off);
            if (lane >= off) { cw += tw; cws += tws; }
        }
        out[(size_t)b * KSEL + htid] = nd;
        out[(size_t)B * KSEL + (size_t)b * KSEL + htid] = cws / cw;
    }
    #undef HBAR
}

extern "C" void kernel_launch(void* const* d_in, const int* in_sizes, int n_in,
                              void* d_out, int out_size)
{
    const float* Q    = (const float*)d_in[0];
    const int*   qsys = (const int*)  d_in[1];
    const float* X    = (const float*)d_in[2];
    const float* Y    = (const float*)d_in[3];
    const int*   sys  = (const int*)  d_in[4];
    const float* W    = (const float*)d_in[5];
    const float* bias = (const float*)d_in[6];
    float* out = (float*)d_out;

    int B = in_sizes[1];
    int N = in_sizes[3];
    int ntiles = (N + TILE_N - 1) / TILE_N;

    const int smem = STAGES * STAGE_BYTES;   // 73728
    cudaFuncSetAttribute(gemm_s8_kernel, cudaFuncAttributeMaxDynamicSharedMemorySize, smem);

    convq_kernel<<<(MAXB * DEMB / 4 + 255) / 256, 256>>>(Q, B * DEMB);
    convx_kernel<<<(N + 7) / 8, 256>>>(X, N);
    gemm_s8_kernel<<<ntiles, 512, smem>>>(B, N, ntiles);
    select_kernel<<<(B + 1) / 2, 512>>>(Q, qsys, X, Y, sys, W, bias, out, B, N, ntiles);
}

// round 11
// speedup vs baseline: 2.0639x; 2.0639x over previous
#include <cuda_runtime.h>
#include <math_constants.h>
#include <cstdint>
#include <cstddef>

#define DEMB 768
#define KSEL 32
#define K2   128               // blockmin threshold rank
#define TILE_N 128
#define KC   32                // k elements per chunk
#define NCH  (DEMB / KC)       // 24
#define MAXB 256
#define MAXN 200000
#define MAXT ((MAXN + TILE_N - 1) / TILE_N)   // 1563
#define CCAP 1024
#define NL   7                 // blockmins cached per thread (7*256 >= MAXT)

#define A_PITCH 48
#define B_PITCH 48
#define A_BYTES (256 * A_PITCH)    // 12288 per stage
#define B_BYTES (128 * B_PITCH)    // 6144 (single fp8 buffer)
#define STAGES 4

// ---- device scratch ----
__device__ __align__(16) uint8_t g_Q8[MAXB * DEMB];
__device__ __align__(16) float   g_S[(size_t)MAXB * (size_t)MAXN];
__device__ __align__(16) float   g_blkmin[MAXB * MAXT];

__device__ __forceinline__ uint32_t smem_u32(const void* p) {
    uint32_t a;
    asm("{ .reg .u64 t; cvta.to.shared.u64 t, %1; cvt.u32.u64 %0, t; }" : "=r"(a) : "l"(p));
    return a;
}
__device__ __forceinline__ void cp16(uint32_t dst, const void* src) {
    asm volatile("cp.async.ca.shared.global [%0], [%1], 16;" :: "r"(dst), "l"(src));
}
#define CP_COMMIT() asm volatile("cp.async.commit_group;" ::: "memory")
#define CP_WAIT2()  asm volatile("cp.async.wait_group 2;" ::: "memory")

__device__ __forceinline__ uint32_t pack_e4m3(float f0, float f1, float f2, float f3) {
    uint16_t lo, hi;
    asm("cvt.rn.satfinite.e4m3x2.f32 %0, %1, %2;" : "=h"(lo) : "f"(f1), "f"(f0));
    asm("cvt.rn.satfinite.e4m3x2.f32 %0, %1, %2;" : "=h"(hi) : "f"(f3), "f"(f2));
    return (uint32_t)lo | ((uint32_t)hi << 16);
}
__device__ __forceinline__ void mma_fp8(float* c, const uint32_t* a, const uint32_t* b) {
    asm volatile(
        "mma.sync.aligned.m16n8k32.row.col.f32.e4m3.e4m3.f32 "
        "{%0,%1,%2,%3}, {%4,%5,%6,%7}, {%8,%9}, {%0,%1,%2,%3};"
        : "+f"(c[0]), "+f"(c[1]), "+f"(c[2]), "+f"(c[3])
        : "r"(a[0]), "r"(a[1]), "r"(a[2]), "r"(a[3]), "r"(b[0]), "r"(b[1]));
}
__device__ __forceinline__ unsigned enc(float f) {
    unsigned u = __float_as_uint(f);
    return (u & 0x80000000u) ? ~u : (u | 0x80000000u);
}
__device__ __forceinline__ float dec(unsigned u) {
    u = (u & 0x80000000u) ? (u & 0x7fffffffu) : ~u;
    return __uint_as_float(u);
}
__device__ __forceinline__ unsigned long long mkkey(float v, int idx) {
    return ((unsigned long long)enc(v) << 32) | (unsigned)idx;
}

// ---------------- Q fp32 -> e4m3 (zero-pad to MAXB rows) ----------------
__global__ void convq_kernel(const float* __restrict__ Q, int total) {
    int i = blockIdx.x * blockDim.x + threadIdx.x;
    if (i < MAXB * DEMB / 4) {
        int e = i * 4;
        float4 v = make_float4(0.f, 0.f, 0.f, 0.f);
        if (e < total) v = *(const float4*)&Q[e];
        ((uint32_t*)g_Q8)[i] = pack_e4m3(v.x, v.y, v.z, v.w);
    }
}

// ---------------- FP8 MMA GEMM, fused X convert + x2, M=256 x N-tile=128 ----------------
__global__ __launch_bounds__(512, 1)
void gemm_fp8_kernel(const float* __restrict__ X, int B, int N, int ntiles)
{
    extern __shared__ __align__(16) char dsm[];
    __shared__ float    x2p[TILE_N];
    __shared__ unsigned bmu[256];

    const int tid  = threadIdx.x;
    const int lane = tid & 31;
    const int warp = tid >> 5;
    const int wm = warp >> 2, wn = warp & 3;
    const int fr = lane >> 2, fc = lane & 3;
    const int n0 = blockIdx.x * TILE_N;

    const uint32_t sb = smem_u32(dsm);
    char* bbuf = dsm + STAGES * A_BYTES;      // single fp8 B buffer

    // A cp.async: 256 rows x 2 x 16B chunks, one per thread
    const int rA = tid >> 1, hA = tid & 1;
    const char* asrc = (const char*)g_Q8 + (size_t)rA * DEMB + hA * 16;
    const uint32_t adst = sb + rA * A_PITCH + hA * 16;

    // B via registers: thread owns (row = tid>>2, col quarter q = tid&3)
    const int rB = tid >> 2, qB = tid & 3;
    const float* bsrc = &X[(size_t)min(n0 + rB, N - 1) * DEMB + qB * 8];

    if (tid < 256) bmu[tid] = 0xFFFFFFFFu;

    // prologue: A stages 0..2; B chunk 0 into regs
    #pragma unroll
    for (int s = 0; s < 3; s++) {
        cp16(adst + s * A_BYTES, asrc + s * KC);
        CP_COMMIT();
    }
    float4 br0 = *(const float4*)bsrc;
    float4 br1 = *(const float4*)(bsrc + 4);

    float acc[4][4][4];
    #pragma unroll
    for (int mi = 0; mi < 4; mi++)
        #pragma unroll
        for (int ni = 0; ni < 4; ni++)
            #pragma unroll
            for (int r = 0; r < 4; r++) acc[mi][ni][r] = 0.f;

    float x2r = 0.f;

    for (int ch = 0; ch < NCH; ch++) {
        const int st = ch & 3;
        CP_WAIT2();
        __syncthreads();   // A stage ready + previous chunk's B-frag reads done

        // convert owned B regs -> fp8 buffer (+ x2 accumulation)
        {
            uint2 pk;
            pk.x = pack_e4m3(br0.x, br0.y, br0.z, br0.w);
            pk.y = pack_e4m3(br1.x, br1.y, br1.z, br1.w);
            *(uint2*)(bbuf + rB * B_PITCH + qB * 8) = pk;
            x2r += fmaf(br0.x, br0.x, fmaf(br0.y, br0.y, fmaf(br0.z, br0.z, br0.w * br0.w)));
            x2r += fmaf(br1.x, br1.x, fmaf(br1.y, br1.y, fmaf(br1.z, br1.z, br1.w * br1.w)));
        }
        // prefetch next B chunk into regs
        if (ch + 1 < NCH) {
            const float* bp = bsrc + (ch + 1) * KC;
            br0 = *(const float4*)bp;
            br1 = *(const float4*)(bp + 4);
        }
        // A cp.async stage ch+3
        if (ch + 3 < NCH)
            cp16(adst + ((ch + 3) & 3) * A_BYTES, asrc + (ch + 3) * KC);
        CP_COMMIT();
        __syncthreads();   // fp8 B visible to all warps

        const char* Ab = dsm + st * A_BYTES;

        // B fragments (conflict-free, pitch 48)
        uint32_t bf[4][2];
        #pragma unroll
        for (int ni = 0; ni < 4; ni++) {
            const int n = wn * 32 + ni * 8 + fr;
            bf[ni][0] = *(const uint32_t*)(bbuf + n * B_PITCH + fc * 4);
            bf[ni][1] = *(const uint32_t*)(bbuf + n * B_PITCH + 16 + fc * 4);
        }

        // A fragments + MMAs
        #pragma unroll
        for (int mi = 0; mi < 4; mi++) {
            const int row = wm * 64 + mi * 16 + fr;
            uint32_t a[4];
            a[0] = *(const uint32_t*)(Ab + row * A_PITCH + fc * 4);
            a[1] = *(const uint32_t*)(Ab + (row + 8) * A_PITCH + fc * 4);
            a[2] = *(const uint32_t*)(Ab + row * A_PITCH + 16 + fc * 4);
            a[3] = *(const uint32_t*)(Ab + (row + 8) * A_PITCH + 16 + fc * 4);
            #pragma unroll
            for (int ni = 0; ni < 4; ni++)
                mma_fp8(acc[mi][ni], a, bf[ni]);
        }
    }

    // x2: reduce over the 4 quarter-lanes owning each row
    x2r += __shfl_xor_sync(0xffffffffu, x2r, 1, 4);
    x2r += __shfl_xor_sync(0xffffffffu, x2r, 2, 4);
    if (qB == 0) x2p[rB] = x2r;
    __syncthreads();

    // ---- epilogue: d2 = x2 - 2*dot, float2 stores + blockmin ----
    #pragma unroll
    for (int mi = 0; mi < 4; mi++) {
        const int R = wm * 64 + mi * 16 + fr;
        float mn0 = CUDART_INF_F, mn1 = CUDART_INF_F;
        #pragma unroll
        for (int ni = 0; ni < 4; ni++) {
            const int c = wn * 32 + ni * 8 + 2 * fc;
            const int n = n0 + c;
            const bool ok0 = n < N, ok1 = (n + 1) < N;
            float x2c = x2p[c], x2d = x2p[c + 1];
            float v0 = fmaf(-2.f, acc[mi][ni][0], x2c);
            float v1 = fmaf(-2.f, acc[mi][ni][1], x2d);
            float v2 = fmaf(-2.f, acc[mi][ni][2], x2c);
            float v3 = fmaf(-2.f, acc[mi][ni][3], x2d);
            if (R < B) {
                if (ok0 && ok1) *(float2*)&g_S[(size_t)R * N + n] = make_float2(v0, v1);
                else if (ok0) g_S[(size_t)R * N + n] = v0;
            }
            if (R + 8 < B) {
                if (ok0 && ok1) *(float2*)&g_S[(size_t)(R + 8) * N + n] = make_float2(v2, v3);
                else if (ok0) g_S[(size_t)(R + 8) * N + n] = v2;
            }
            if (ok0) { mn0 = fminf(mn0, v0); mn1 = fminf(mn1, v2); }
            if (ok1) { mn0 = fminf(mn0, v1); mn1 = fminf(mn1, v3); }
        }
        #pragma unroll
        for (int off = 1; off < 4; off <<= 1) {
            mn0 = fminf(mn0, __shfl_xor_sync(0xffffffffu, mn0, off));
            mn1 = fminf(mn1, __shfl_xor_sync(0xffffffffu, mn1, off));
        }
        if (fc == 0) {
            atomicMin(&bmu[R], enc(mn0));
            atomicMin(&bmu[R + 8], enc(mn1));
        }
    }
    __syncthreads();
    if (tid < 256)
        g_blkmin[tid * ntiles + blockIdx.x] = dec(bmu[tid]);
}

// ---------------- select: 2 queries/CTA, binary-search t0, float4 refine ----------------
__global__ __launch_bounds__(512)
void select_kernel(const float* __restrict__ Q, const int* __restrict__ qsys,
                   const float* __restrict__ X, const float* __restrict__ Y,
                   const int* __restrict__ sys, const float* __restrict__ W,
                   const float* __restrict__ bias, float* __restrict__ out,
                   int B, int N, int ntiles)
{
    __shared__ float qs[2][DEMB];
    __shared__ unsigned long long buf[2][CCAP];
    __shared__ int   cand[2][CCAP];
    __shared__ int   blist[2][CCAP];
    __shared__ float red[2][8];
    __shared__ int   wcnt[2][8];
    __shared__ int   sh_cnt[2], sh_nblk[2];

    const int tid  = threadIdx.x;
    const int half = tid >> 8;
    const int htid = tid & 255;
    const int hw   = htid >> 5;
    const int lane = tid & 31;
    const int hbar = half + 1;
    const int b    = blockIdx.x * 2 + half;

    #define HBAR() asm volatile("bar.sync %0, 256;" :: "r"(hbar) : "memory")

    // ---- query row + q2 ----
    float q2p = 0.f;
    for (int k = htid; k < DEMB; k += 256) {
        float v = Q[(size_t)b * DEMB + k];
        qs[half][k] = v; q2p = fmaf(v, v, q2p);
    }
    #pragma unroll
    for (int off = 16; off > 0; off >>= 1) q2p += __shfl_xor_sync(0xffffffffu, q2p, off);
    if (lane == 0) red[half][hw] = q2p;
    if (htid == 0) { sh_cnt[half] = 0; sh_nblk[half] = 0; }
    HBAR();
    float q2 = 0.f;
    #pragma unroll
    for (int w = 0; w < 8; w++) q2 += red[half][w];

    // ---- cache blockmins (encoded) ----
    const float* bmrow = &g_blkmin[b * ntiles];
    uint32_t loc[NL];
    #pragma unroll
    for (int i = 0; i < NL; i++) {
        int idx = i * 256 + htid;
        loc[i] = (idx < ntiles) ? enc(bmrow[idx]) : 0xFFFFFFFFu;
    }

    // ---- bitwise binary search for t0enc = K2-th smallest ----
    uint32_t r = 0;
    for (int bitp = 31; bitp >= 0; bitp--) {
        uint32_t trial = r | (1u << bitp);
        int c = 0;
        #pragma unroll
        for (int i = 0; i < NL; i++) c += (loc[i] < trial);
        #pragma unroll
        for (int off = 16; off > 0; off >>= 1) c += __shfl_xor_sync(0xffffffffu, c, off);
        if (lane == 0) wcnt[half][hw] = c;
        HBAR();
        int tot = 0;
        #pragma unroll
        for (int w = 0; w < 8; w++) tot += wcnt[half][w];
        if (tot < K2) r = trial;
        HBAR();
    }
    const uint32_t t0enc = r;
    const float t0 = dec(t0enc);

    // ---- qualifying blocks ----
    #pragma unroll
    for (int i = 0; i < NL; i++) {
        int idx = i * 256 + htid;
        if (idx < ntiles && loc[i] <= t0enc) {
            int p = atomicAdd(&sh_nblk[half], 1);
            if (p < CCAP) blist[half][p] = idx;
        }
    }
    HBAR();
    int nblk = sh_nblk[half]; if (nblk > CCAP) nblk = CCAP;

    // ---- gather candidate indices ----
    const float* srow = &g_S[(size_t)b * N];
    for (int e = htid; e < nblk * TILE_N; e += 256) {
        int blk = blist[half][e >> 7];
        int n = blk * TILE_N + (e & (TILE_N - 1));
        if (n < N) {
            float v = srow[n];
            if (v <= t0) {
                int p = atomicAdd(&sh_cnt[half], 1);
                if (p < CCAP) cand[half][p] = n;
            }
        }
    }
    HBAR();
    int cnt = sh_cnt[half]; if (cnt > CCAP) cnt = CCAP;

    int P = 64; while (P < cnt) P <<= 1;
    for (int i = htid; i < P; i += 256) buf[half][i] = ~0ULL;
    HBAR();

    // ---- exact fp32 refine (float4, MLP=6) ----
    const float4* qs4 = (const float4*)qs[half];
    for (int c = hw; c < cnt; c += 8) {
        const int idx = cand[half][c];
        const float4* xr4 = (const float4*)&X[(size_t)idx * DEMB];
        float dot = 0.f, xx = 0.f;
        #pragma unroll
        for (int k = lane; k < DEMB / 4; k += 32) {
            float4 xv = xr4[k];
            float4 qv = qs4[k];
            dot = fmaf(xv.x, qv.x, fmaf(xv.y, qv.y, fmaf(xv.z, qv.z, fmaf(xv.w, qv.w, dot))));
            xx  = fmaf(xv.x, xv.x, fmaf(xv.y, xv.y, fmaf(xv.z, xv.z, fmaf(xv.w, xv.w, xx))));
        }
        #pragma unroll
        for (int off = 16; off > 0; off >>= 1) {
            dot += __shfl_xor_sync(0xffffffffu, dot, off);
            xx  += __shfl_xor_sync(0xffffffffu, xx,  off);
        }
        if (lane == 0) buf[half][c] = mkkey(fmaf(-2.f, dot, q2 + xx), idx);
    }
    HBAR();

    // ---- bitonic sort exact keys ----
    for (int k = 2; k <= P; k <<= 1)
        for (int j = k >> 1; j > 0; j >>= 1) {
            for (int i = htid; i < P; i += 256) {
                int ixj = i ^ j;
                if (ixj > i) {
                    unsigned long long a = buf[half][i], c = buf[half][ixj];
                    if ((a > c) == ((i & k) == 0)) { buf[half][i] = c; buf[half][ixj] = a; }
                }
            }
            HBAR();
        }

    // ---- local layer + prefix softmax ----
    if (htid < KSEL) {
        unsigned long long key = buf[half][htid];
        float d2v = dec((unsigned)(key >> 32));
        int   idx = (int)(key & 0xffffffffu);
        float sc  = Y[idx];
        float nd  = (sys[idx] == qsys[b]) ? fmaf(d2v, W[1], bias[1]) : fmaf(d2v, W[0], bias[0]);
        float neg = -nd;
        float mmax = neg;
        #pragma unroll
        for (int off = 16; off > 0; off >>= 1)
            mmax = fmaxf(mmax, __shfl_xor_sync(0xffffffffu, mmax, off));
        float w  = expf(neg - mmax);
        float ws = w * sc;
        float cw = w, cws = ws;
        #pragma unroll
        for (int off = 1; off < KSEL; off <<= 1) {
            float tw  = __shfl_up_sync(0xffffffffu, cw,  off);
            float tws = __shfl_up_sync(0xffffffffu, cws, off);
            if (lane >= off) { cw += tw; cws += tws; }
        }
        out[(size_t)b * KSEL + htid] = nd;
        out[(size_t)B * KSEL + (size_t)b * KSEL + htid] = cws / cw;
    }
    #undef HBAR
}

extern "C" void kernel_launch(void* const* d_in, const int* in_sizes, int n_in,
                              void* d_out, int out_size)
{
    const float* Q    = (const float*)d_in[0];
    const int*   qsys = (const int*)  d_in[1];
    const float* X    = (const float*)d_in[2];
    const float* Y    = (const float*)d_in[3];
    const int*   sys  = (const int*)  d_in[4];
    const float* W    = (const float*)d_in[5];
    const float* bias = (const float*)d_in[6];
    float* out = (float*)d_out;

    int B = in_sizes[1];
    int N = in_sizes[3];
    int ntiles = (N + TILE_N - 1) / TILE_N;

    const int smem = STAGES * A_BYTES + B_BYTES;   // 55296
    cudaFuncSetAttribute(gemm_fp8_kernel, cudaFuncAttributeMaxDynamicSharedMemorySize, smem);

    convq_kernel<<<(MAXB * DEMB / 4 + 255) / 256, 256>>>(Q, B * DEMB);
    gemm_fp8_kernel<<<ntiles, 512, smem>>>(X, B, N, ntiles);
    select_kernel<<<(B + 1) / 2, 512>>>(Q, qsys, X, Y, sys, W, bias, out, B, N, ntiles);
}